// round 1
// baseline (speedup 1.0000x reference)
#include <cuda_runtime.h>
#include <cstdint>

// PlaceCellNetwork: Y = 50 fixed-point iterations of
//   z_j = C_j + sum_i max(z_i,0) * G[i][j],  Y_j = inv_j * max(z_j, 0)
// with G = invden_i * ((i==j) ? (1-dt) : -dt*M[i][j]),
//      C_j = dt*((Wx)_j - b_j) - lbd1, invden_j = 1/(lbd2 + M[j][j]).
// Early exit in the reference never triggers (contraction 0.945 => err_50 ~3e-3 > 1e-4),
// so exactly 50 iterations, rows fully independent. One thread per row, packed f32x2 FMA.

#define DT    0.05f
#define LBD1  0.005f
#define LBD2  0.005f
#define NITER 50

__device__ __align__(16) float g_G2[100];  // pairs: (i*5+p)*2 -> {G[i][2p], G[i][2p+1]}
__device__ __align__(16) float g_W2[52];   // pairs: (k*5+p)*2 -> {dt*W[2p][k], dt*W[2p+1][k]}
__device__ __align__(16) float g_C0[12];   // C0_j = -dt*b_j - lbd1 (pairs linear in j)
__device__ __align__(16) float g_inv[12];  // 1/(lbd2 + M[j][j])

__global__ void setup_kernel(const float* __restrict__ W,
                             const float* __restrict__ M,
                             const float* __restrict__ b) {
    int t = threadIdx.x;
    if (t < 100) {
        int q = t >> 1, half = t & 1;
        int i = q / 5, p = q % 5, j = 2 * p + half;
        float H = (i == j) ? (1.0f - DT) : (-DT * M[i * 10 + j]);
        g_G2[t] = H / (LBD2 + M[i * 10 + i]);
    }
    if (t < 50) {
        int q = t >> 1, half = t & 1;
        int k = q / 5, p = q % 5, j = 2 * p + half;
        g_W2[t] = DT * W[j * 5 + k];
    }
    if (t < 10) {
        g_C0[t]  = -DT * b[t] - LBD1;
        g_inv[t] = 1.0f / (LBD2 + M[t * 10 + t]);
    }
}

typedef unsigned long long u64;

__device__ __forceinline__ u64 f2fma(u64 a, u64 b, u64 c) {
    u64 d;
    asm("fma.rn.f32x2 %0, %1, %2, %3;" : "=l"(d) : "l"(a), "l"(b), "l"(c));
    return d;
}
__device__ __forceinline__ u64 f2pack(float lo, float hi) {
    u64 d;
    asm("mov.b64 %0, {%1, %2};" : "=l"(d) : "f"(lo), "f"(hi));
    return d;
}
__device__ __forceinline__ void f2unpack(u64 v, float& lo, float& hi) {
    asm("mov.b64 {%0, %1}, %2;" : "=f"(lo), "=f"(hi) : "l"(v));
}

__global__ __launch_bounds__(128)
void pcn_kernel(const float* __restrict__ X, float* __restrict__ Yout, int rows) {
    int r = blockIdx.x * blockDim.x + threadIdx.x;
    if (r >= rows) return;

    // Broadcast loads of the folded 10x10 coupling matrix (L1-resident, 800 B total)
    const u64* G2p = (const u64*)g_G2;
    u64 G[50];
#pragma unroll
    for (int q = 0; q < 50; q++) G[q] = G2p[q];

    // Row input
    float x[5];
#pragma unroll
    for (int k = 0; k < 5; k++) x[k] = X[(size_t)r * 5 + k];

    // C2_p = C0_p + sum_k (x_k,x_k) * W2[k][p]   (25 packed FMAs)
    const u64* C0p = (const u64*)g_C0;
    const u64* W2p = (const u64*)g_W2;
    u64 C2[5];
#pragma unroll
    for (int p = 0; p < 5; p++) C2[p] = C0p[p];
#pragma unroll
    for (int k = 0; k < 5; k++) {
        u64 xd = f2pack(x[k], x[k]);
#pragma unroll
        for (int p = 0; p < 5; p++)
            C2[p] = f2fma(xd, W2p[k * 5 + p], C2[p]);
    }

    // z^(1) = C
    u64 z[5];
#pragma unroll
    for (int p = 0; p < 5; p++) z[p] = C2[p];

    // 49 more updates: V = max(z,0) (dup'd per scalar), z = C + V * G
#pragma unroll 1
    for (int it = 0; it < NITER - 1; it++) {
        u64 Vd[10];
#pragma unroll
        for (int p = 0; p < 5; p++) {
            float lo, hi;
            f2unpack(z[p], lo, hi);
            float v0 = fmaxf(lo, 0.0f);
            float v1 = fmaxf(hi, 0.0f);
            Vd[2 * p]     = f2pack(v0, v0);
            Vd[2 * p + 1] = f2pack(v1, v1);
        }
#pragma unroll
        for (int p = 0; p < 5; p++) z[p] = C2[p];
#pragma unroll
        for (int i = 0; i < 10; i++) {
#pragma unroll
            for (int p = 0; p < 5; p++)
                z[p] = f2fma(Vd[i], G[i * 5 + p], z[p]);
        }
    }

    // Final activation + scale, 8-byte vector stores (row offset 40B -> 8B aligned)
    float2* out = (float2*)Yout;
#pragma unroll
    for (int p = 0; p < 5; p++) {
        float lo, hi;
        f2unpack(z[p], lo, hi);
        float2 y;
        y.x = fmaxf(lo, 0.0f) * g_inv[2 * p];
        y.y = fmaxf(hi, 0.0f) * g_inv[2 * p + 1];
        out[(size_t)r * 5 + p] = y;
    }
}

extern "C" void kernel_launch(void* const* d_in, const int* in_sizes, int n_in,
                              void* d_out, int out_size) {
    // Identify inputs by element count (robust to ordering): X=B*5, W=50, M=100, b=10
    const float *X = nullptr, *W = nullptr, *M = nullptr, *b = nullptr;
    for (int i = 0; i < n_in; i++) {
        int s = in_sizes[i];
        const float* p = (const float*)d_in[i];
        if (s == 100) M = p;
        else if (s == 50) W = p;
        else if (s == 10) b = p;
        else X = p;
    }
    int rows = 0;
    for (int i = 0; i < n_in; i++)
        if ((const float*)d_in[i] == X) rows = in_sizes[i] / 5;

    setup_kernel<<<1, 128>>>(W, M, b);

    const int threads = 128;
    int blocks = (rows + threads - 1) / threads;
    pcn_kernel<<<blocks, threads>>>(X, (float*)d_out, rows);
}